// round 7
// baseline (speedup 1.0000x reference)
#include <cuda_runtime.h>
#include <cuda_bf16.h>
#include <cstdint>

// ---------------- problem constants ----------------
#define NB 4
#define LDIM 3600
#define SDIM 3600
#define CDIM 256
#define LPAD 3712            // 29 * 128
#define H0 60
#define W0 60
#define BORDER 2
#define THR 0.2f
#define SIM_SCALE 0.0390625f // 1/(C * TEMP) = 1/25.6

#define NLTOT (NB * LDIM)
#define NSTOT (NB * SDIM)

// ---------------- device scratch (no runtime alloc) ----------------
__device__ __align__(128) __nv_bfloat16 g_f0h[NB * LPAD * CDIM];
__device__ __align__(128) __nv_bfloat16 g_f0l[NB * LPAD * CDIM];
__device__ __align__(128) __nv_bfloat16 g_f1h[NB * LPAD * CDIM];
__device__ __align__(128) __nv_bfloat16 g_f1l[NB * LPAD * CDIM];
__device__ float               g_rowsum[NLTOT];   // sum_s exp(sim)
__device__ float               g_colsum[NSTOT];   // sum_l exp(sim)
__device__ unsigned int        g_colmaxU[NSTOT];  // bits of max_l u, u=(e*e)*invSr
__device__ unsigned long long  g_rowbest[NLTOT];  // (conf_bits<<32)|(S-1-j)

// ---------------- helpers ----------------
__device__ __forceinline__ uint32_t smem_u32(const void* p) {
    uint32_t a;
    asm("{ .reg .u64 t; cvta.to.shared.u64 t, %1; cvt.u32.u64 %0, t; }"
        : "=r"(a) : "l"(p));
    return a;
}

#define LDSM4(R, ADDR) \
    asm volatile("ldmatrix.sync.aligned.m8n8.x4.shared.b16 {%0,%1,%2,%3}, [%4];" \
        : "=r"((R)[0]), "=r"((R)[1]), "=r"((R)[2]), "=r"((R)[3]) : "r"(ADDR))

#define MMA16816(D, A, B) \
    asm volatile("mma.sync.aligned.m16n8k16.row.col.f32.bf16.bf16.f32 " \
        "{%0,%1,%2,%3},{%4,%5,%6,%7},{%8,%9},{%0,%1,%2,%3};" \
        : "+f"((D)[0]), "+f"((D)[1]), "+f"((D)[2]), "+f"((D)[3]) \
        : "r"((A)[0]), "r"((A)[1]), "r"((A)[2]), "r"((A)[3]), \
          "r"((B)[0]), "r"((B)[1]))

__device__ __forceinline__ void cp16(uint32_t sp, const void* gp) {
    asm volatile("cp.async.cg.shared.global [%0], [%1], 16;"
                 :: "r"(sp), "l"(__cvta_generic_to_global(gp)));
}

// ---------------------------------------------------------------------------
// K0: fp32 -> split bf16 (hi + lo), padded rows [LDIM, LPAD) zeroed.
//     which==0 additionally zeroes the reduction scratch.
// ---------------------------------------------------------------------------
__global__ __launch_bounds__(256)
void convert_kernel(const float* __restrict__ src, int which) {
    int idx = blockIdx.x * blockDim.x + threadIdx.x;   // NB*LPAD*64 float4 groups
    if (which == 0) {
        if (idx < NLTOT) { g_rowsum[idx] = 0.f; g_rowbest[idx] = 0ull; }
        if (idx < NSTOT) { g_colsum[idx] = 0.f; g_colmaxU[idx] = 0u; }
    }
    int k4 = idx & 63;
    int r  = (idx >> 6) % LPAD;
    int b  = idx / (64 * LPAD);
    if (b >= NB) return;

    __nv_bfloat16* hi = which ? g_f1h : g_f0h;
    __nv_bfloat16* lo = which ? g_f1l : g_f0l;

    float4 v = make_float4(0.f, 0.f, 0.f, 0.f);
    if (r < LDIM)
        v = *reinterpret_cast<const float4*>(src + ((size_t)(b * LDIM + r)) * CDIM + k4 * 4);

    float x[4] = {v.x, v.y, v.z, v.w};
    __nv_bfloat16 h[4], l[4];
#pragma unroll
    for (int i = 0; i < 4; i++) {
        h[i] = __float2bfloat16(x[i]);
        l[i] = __float2bfloat16(x[i] - __bfloat162float(h[i]));
    }
    size_t o = ((size_t)(b * LPAD + r)) * CDIM + k4 * 4;
    reinterpret_cast<__nv_bfloat162*>(hi + o)[0] = __halves2bfloat162(h[0], h[1]);
    reinterpret_cast<__nv_bfloat162*>(hi + o)[1] = __halves2bfloat162(h[2], h[3]);
    reinterpret_cast<__nv_bfloat162*>(lo + o)[0] = __halves2bfloat162(l[0], l[1]);
    reinterpret_cast<__nv_bfloat162*>(lo + o)[1] = __halves2bfloat162(l[2], l[3]);
}

// ---------------------------------------------------------------------------
// K1: split-bf16 HMMA GEMM, 5-stage cp.async pipeline (BK=16),
//     + fused exp + row/col exp-sum accumulation.
// ---------------------------------------------------------------------------
#define NSTAGE 5
#define MAT4K 4096                   // bytes per matrix per stage (128 rows x 32B)
#define STB   (4 * MAT4K)            // 16384 B per stage
#define GEMM_SMEM (NSTAGE * STB)     // 81920 B

__global__ __launch_bounds__(256, 2)
void gemm_kernel(float* __restrict__ sim)
{
    extern __shared__ __align__(16) char dsm[];
    const int tid = threadIdx.x;
    const int b  = blockIdx.z;
    const int m0 = blockIdx.y * 128;
    const int n0 = blockIdx.x * 128;
    const uint32_t sbase = smem_u32(dsm);

    const __nv_bfloat16* gAh = g_f0h + (size_t)(b * LPAD + m0) * CDIM;
    const __nv_bfloat16* gAl = g_f0l + (size_t)(b * LPAD + m0) * CDIM;
    const __nv_bfloat16* gBh = g_f1h + (size_t)(b * LPAD + n0) * CDIM;
    const __nv_bfloat16* gBl = g_f1l + (size_t)(b * LPAD + n0) * CDIM;

    // 4 x 16B chunks per thread per stage (1024 chunks = 16KB)
    int l_mat[4], l_r[4], l_c[4];
#pragma unroll
    for (int i = 0; i < 4; i++) {
        int id = tid + i * 256;
        l_mat[i] = id >> 8;          // 0..3 (Ah, Al, Bh, Bl)
        l_r[i]   = (id >> 1) & 127;  // row
        l_c[i]   = id & 1;           // 16B half of 32B row
    }

#define LOAD_BODY(KC, BUF) do {                                               \
        int koff = (KC) * 16;                                                 \
        _Pragma("unroll")                                                     \
        for (int i = 0; i < 4; i++) {                                         \
            const __nv_bfloat16* bp =                                         \
                (l_mat[i] == 0) ? gAh : (l_mat[i] == 1) ? gAl :               \
                (l_mat[i] == 2) ? gBh : gBl;                                  \
            const __nv_bfloat16* gp = bp + (size_t)l_r[i] * CDIM + koff + l_c[i] * 8; \
            uint32_t sp = sbase + (BUF) * STB + l_mat[i] * MAT4K              \
                        + l_r[i] * 32 + l_c[i] * 16;                          \
            cp16(sp, gp);                                                     \
        }                                                                     \
    } while (0)

    float acc[4][4][4];
#pragma unroll
    for (int mt = 0; mt < 4; mt++)
#pragma unroll
        for (int nt = 0; nt < 4; nt++)
#pragma unroll
            for (int q = 0; q < 4; q++) acc[mt][nt][q] = 0.f;

    // prologue: prefetch stages 0..3, one commit group each
#pragma unroll
    for (int p = 0; p < NSTAGE - 1; p++) {
        LOAD_BODY(p, p);
        asm volatile("cp.async.commit_group;" ::: "memory");
    }

    const int lane = tid & 31;
    const int wid  = tid >> 5;
    const int mwb  = (wid & 1) * 64;
    const int nwb  = (wid >> 1) * 32;
    const int a_row  = lane & 15;
    const int a_col8 = (lane & 16) >> 1;
    const int b_row  = (lane & 7) + ((lane & 16) >> 1);
    const int b_col8 = lane & 8;

    const uint32_t aoff = (mwb + a_row) * 32 + a_col8 * 2;
    const uint32_t boff = (nwb + b_row) * 32 + b_col8 * 2;

    for (int kc = 0; kc < 16; kc++) {
        // stage kc ready once <= NSTAGE-2 groups outstanding
        asm volatile("cp.async.wait_group %0;" :: "n"(NSTAGE - 2) : "memory");
        __syncthreads();   // all threads done with stage kc-1 reads + stage kc visible

        if (kc + NSTAGE - 1 < 16) {
            int bufn = (kc + NSTAGE - 1) % NSTAGE;
            LOAD_BODY(kc + NSTAGE - 1, bufn);
        }
        asm volatile("cp.async.commit_group;" ::: "memory");  // empty group ok

        const uint32_t st = sbase + (kc % NSTAGE) * STB;

        uint32_t ah[4][4], bh[4][2];
#pragma unroll
        for (int mt = 0; mt < 4; mt++)
            LDSM4(ah[mt], st + aoff + mt * 16 * 32);
#pragma unroll
        for (int bp = 0; bp < 2; bp++) {
            uint32_t r[4];
            LDSM4(r, st + 2 * MAT4K + boff + bp * 16 * 32);
            bh[bp * 2][0] = r[0]; bh[bp * 2][1] = r[1];
            bh[bp * 2 + 1][0] = r[2]; bh[bp * 2 + 1][1] = r[3];
        }
#pragma unroll
        for (int mt = 0; mt < 4; mt++)
#pragma unroll
            for (int nt = 0; nt < 4; nt++)
                MMA16816(acc[mt][nt], ah[mt], bh[nt]);
        {
            uint32_t bl[4][2];
#pragma unroll
            for (int bp = 0; bp < 2; bp++) {
                uint32_t r[4];
                LDSM4(r, st + 3 * MAT4K + boff + bp * 16 * 32);
                bl[bp * 2][0] = r[0]; bl[bp * 2][1] = r[1];
                bl[bp * 2 + 1][0] = r[2]; bl[bp * 2 + 1][1] = r[3];
            }
#pragma unroll
            for (int mt = 0; mt < 4; mt++)
#pragma unroll
                for (int nt = 0; nt < 4; nt++)
                    MMA16816(acc[mt][nt], ah[mt], bl[nt]);
        }
        {
            uint32_t al[4][4];
#pragma unroll
            for (int mt = 0; mt < 4; mt++)
                LDSM4(al[mt], st + MAT4K + aoff + mt * 16 * 32);
#pragma unroll
            for (int mt = 0; mt < 4; mt++)
#pragma unroll
                for (int nt = 0; nt < 4; nt++)
                    MMA16816(acc[mt][nt], al[mt], bh[nt]);
        }
    }

    // ---- fused epilogue: e = exp(sim*scale); store e; accumulate sums ----
    float* simb = sim + (size_t)b * LDIM * SDIM;
    float rsum[4][2];
    float csum[4][2];
#pragma unroll
    for (int i = 0; i < 4; i++) {
        rsum[i][0] = rsum[i][1] = 0.f;
        csum[i][0] = csum[i][1] = 0.f;
    }

#pragma unroll
    for (int mt = 0; mt < 4; mt++) {
        int rr = m0 + mwb + mt * 16 + (lane >> 2);
        bool vr0 = rr < LDIM;
        bool vr1 = (rr + 8) < LDIM;
#pragma unroll
        for (int nt = 0; nt < 4; nt++) {
            int cc = n0 + nwb + nt * 8 + (lane & 3) * 2;
            bool vc = (cc + 1) < SDIM;
            float e0 = __expf(acc[mt][nt][0] * SIM_SCALE);
            float e1 = __expf(acc[mt][nt][1] * SIM_SCALE);
            float e2 = __expf(acc[mt][nt][2] * SIM_SCALE);
            float e3 = __expf(acc[mt][nt][3] * SIM_SCALE);
            if (vc) {
                if (vr0)
                    *reinterpret_cast<float2*>(simb + (size_t)rr * SDIM + cc)
                        = make_float2(e0, e1);
                if (vr1)
                    *reinterpret_cast<float2*>(simb + (size_t)(rr + 8) * SDIM + cc)
                        = make_float2(e2, e3);
                rsum[mt][0] += e0 + e1;
                rsum[mt][1] += e2 + e3;
                csum[nt][0] += (vr0 ? e0 : 0.f) + (vr1 ? e2 : 0.f);
                csum[nt][1] += (vr0 ? e1 : 0.f) + (vr1 ? e3 : 0.f);
            }
        }
    }

#pragma unroll
    for (int mt = 0; mt < 4; mt++)
#pragma unroll
        for (int h = 0; h < 2; h++) {
            float v = rsum[mt][h];
            v += __shfl_xor_sync(0xffffffffu, v, 1);
            v += __shfl_xor_sync(0xffffffffu, v, 2);
            if ((lane & 3) == 0) {
                int rr = m0 + mwb + mt * 16 + (lane >> 2) + h * 8;
                if (rr < LDIM) atomicAdd(&g_rowsum[b * LDIM + rr], v);
            }
        }
#pragma unroll
    for (int nt = 0; nt < 4; nt++)
#pragma unroll
        for (int q1 = 0; q1 < 2; q1++) {
            float v = csum[nt][q1];
            v += __shfl_xor_sync(0xffffffffu, v, 4);
            v += __shfl_xor_sync(0xffffffffu, v, 8);
            v += __shfl_xor_sync(0xffffffffu, v, 16);
            if (lane < 4) {
                int cc = n0 + nwb + nt * 8 + lane * 2 + q1;
                if (cc < SDIM) atomicAdd(&g_colsum[b * SDIM + cc], v);
            }
        }
#undef LOAD_BODY
}

// ---------------------------------------------------------------------------
// K2: conf pass.  invSc in shared memory; 5 blocks/SM via launch bounds.
//       u = (e*e) * invSr;  c = u * invSc;  write c in place
// ---------------------------------------------------------------------------
#define RPB 12           // rows per block (3600 = 300 * 12)
#define S4  (SDIM / 4)   // 900 float4 per row

__global__ __launch_bounds__(256, 5)
void conf_kernel(float* __restrict__ sim) {
    __shared__ __align__(16) float sInv[SDIM];   // 14.4 KB

    const int tid = threadIdx.x;
    const int b   = blockIdx.y;
    const int r0  = blockIdx.x * RPB;

    for (int i = tid; i < S4; i += 256) {
        float4 cs = *reinterpret_cast<const float4*>(g_colsum + b * SDIM + 4 * i);
        float4 iv = make_float4(1.0f / cs.x, 1.0f / cs.y, 1.0f / cs.z, 1.0f / cs.w);
        *reinterpret_cast<float4*>(sInv + 4 * i) = iv;
    }
    __syncthreads();

    uint32_t cmU[4][4];
#pragma unroll
    for (int i = 0; i < 4; i++)
#pragma unroll
        for (int c = 0; c < 4; c++) cmU[i][c] = 0u;

    for (int r = 0; r < RPB; r++) {
        const int l = r0 + r;
        float* row = sim + ((size_t)(b * LDIM + l)) * SDIM;
        const float invSr = 1.0f / g_rowsum[b * LDIM + l];
        float best = -1.f;
        int   bj   = 0;
#pragma unroll
        for (int i = 0; i < 4; i++) {
            int s4 = tid + i * 256;
            if (s4 < S4) {
                float4 e4 = *reinterpret_cast<const float4*>(row + 4 * s4);
                float4 iv = *reinterpret_cast<const float4*>(sInv + 4 * s4);
                float ev[4] = {e4.x, e4.y, e4.z, e4.w};
                float ivv[4] = {iv.x, iv.y, iv.z, iv.w};
                float cv[4];
#pragma unroll
                for (int c = 0; c < 4; c++) {
                    float u = (ev[c] * ev[c]) * invSr;
                    float cf = u * ivv[c];
                    cv[c] = cf;
                    uint32_t ub = __float_as_uint(u);
                    if (ub > cmU[i][c]) cmU[i][c] = ub;
                    if (cf > best) { best = cf; bj = 4 * s4 + c; }
                }
                *reinterpret_cast<float4*>(row + 4 * s4) =
                    make_float4(cv[0], cv[1], cv[2], cv[3]);
            }
        }
#pragma unroll
        for (int o = 16; o > 0; o >>= 1) {
            float v2 = __shfl_xor_sync(0xffffffffu, best, o);
            int   j2 = __shfl_xor_sync(0xffffffffu, bj, o);
            if (v2 > best || (v2 == best && j2 < bj)) { best = v2; bj = j2; }
        }
        if ((tid & 31) == 0) {
            unsigned long long pk =
                ((unsigned long long)__float_as_uint(best) << 32) |
                (unsigned int)(SDIM - 1 - bj);
            atomicMax(&g_rowbest[b * LDIM + l], pk);
        }
    }
#pragma unroll
    for (int i = 0; i < 4; i++) {
        int s4 = tid + i * 256;
        if (s4 < S4) {
#pragma unroll
            for (int c = 0; c < 4; c++)
                atomicMax(&g_colmaxU[b * SDIM + 4 * s4 + c], cmU[i][c]);
        }
    }
}

// ---------------------------------------------------------------------------
// K3: finalize matches
// ---------------------------------------------------------------------------
__device__ __forceinline__ bool border_ok(int idx) {
    int r = idx / W0, c = idx % W0;
    return (r >= BORDER) && (r < H0 - BORDER) && (c >= BORDER) && (c < W0 - BORDER);
}

__global__ void finalize_kernel(float* __restrict__ out_maskv,
                                float* __restrict__ out_ids,
                                float* __restrict__ out_mconf) {
    int idx = blockIdx.x * blockDim.x + threadIdx.x;
    if (idx >= NLTOT) return;
    int b = idx / LDIM;
    int l = idx - b * LDIM;

    unsigned long long pk = g_rowbest[idx];
    float c = __uint_as_float((unsigned int)(pk >> 32));
    int   j = SDIM - 1 - (int)(pk & 0xffffffffu);

    float umax  = __uint_as_float(g_colmaxU[b * SDIM + j]);
    float invSc = 1.0f / g_colsum[b * SDIM + j];
    float cmax  = umax * invSc;   // identical multiply order as conf_kernel

    bool ok = (c > THR) && border_ok(l) && border_ok(j) && (c == cmax);

    out_maskv[idx] = ok ? 1.f : 0.f;
    out_ids[idx]   = ok ? (float)j : 0.f;
    out_mconf[idx] = ok ? c : 0.f;
}

// ---------------------------------------------------------------------------
extern "C" void kernel_launch(void* const* d_in, const int* in_sizes, int n_in,
                              void* d_out, int out_size) {
    const float* f0 = (const float*)d_in[0];
    const float* f1 = (const float*)d_in[1];
    (void)in_sizes; (void)n_in; (void)out_size;

    float* conf  = (float*)d_out;                      // [NB, L, S]
    float* maskv = conf  + (size_t)NB * LDIM * SDIM;   // [NB, L]
    float* ids   = maskv + NB * LDIM;
    float* mconf = ids   + NB * LDIM;

    const int cvt_blocks = (NB * LPAD * 64 + 255) / 256;
    convert_kernel<<<cvt_blocks, 256>>>(f0, 0);   // also zeroes reductions
    convert_kernel<<<cvt_blocks, 256>>>(f1, 1);

    static bool attr_set = false;
    if (!attr_set) {
        cudaFuncSetAttribute(gemm_kernel,
                             cudaFuncAttributeMaxDynamicSharedMemorySize, GEMM_SMEM);
        attr_set = true;
    }
    dim3 gGemm(LPAD / 128, LPAD / 128, NB);            // 29 x 29 x 4
    gemm_kernel<<<gGemm, 256, GEMM_SMEM>>>(conf);

    conf_kernel<<<dim3(LDIM / RPB, NB), 256>>>(conf);
    finalize_kernel<<<(NLTOT + 255) / 256, 256>>>(maskv, ids, mconf);
}

// round 8
// speedup vs baseline: 1.2305x; 1.2305x over previous
#include <cuda_runtime.h>
#include <cuda_bf16.h>
#include <cstdint>

// ---------------- problem constants ----------------
#define NB 4
#define LDIM 3600
#define SDIM 3600
#define CDIM 256
#define LPAD 3712            // 29 * 128
#define H0 60
#define W0 60
#define BORDER 2
#define THR 0.2f
#define SIM_SCALE 0.0390625f // 1/(C * TEMP) = 1/25.6

#define NLTOT (NB * LDIM)
#define NSTOT (NB * SDIM)

// ---------------- device scratch (no runtime alloc) ----------------
__device__ __align__(128) __nv_bfloat16 g_f0h[NB * LPAD * CDIM];
__device__ __align__(128) __nv_bfloat16 g_f0l[NB * LPAD * CDIM];
__device__ __align__(128) __nv_bfloat16 g_f1h[NB * LPAD * CDIM];
__device__ __align__(128) __nv_bfloat16 g_f1l[NB * LPAD * CDIM];
__device__ float               g_rowsum[NLTOT];   // sum_s exp(sim)
__device__ float               g_colsum[NSTOT];   // sum_l exp(sim)
__device__ unsigned int        g_colmaxU[NSTOT];  // bits of max_l u, u=(e*e)*invSr
__device__ unsigned long long  g_rowbest[NLTOT];  // (conf_bits<<32)|(S-1-j)

// ---------------- helpers ----------------
__device__ __forceinline__ uint32_t smem_u32(const void* p) {
    uint32_t a;
    asm("{ .reg .u64 t; cvta.to.shared.u64 t, %1; cvt.u32.u64 %0, t; }"
        : "=r"(a) : "l"(p));
    return a;
}

#define LDSM4(R, ADDR) \
    asm volatile("ldmatrix.sync.aligned.m8n8.x4.shared.b16 {%0,%1,%2,%3}, [%4];" \
        : "=r"((R)[0]), "=r"((R)[1]), "=r"((R)[2]), "=r"((R)[3]) : "r"(ADDR))

#define MMA16816(D, A, B) \
    asm volatile("mma.sync.aligned.m16n8k16.row.col.f32.bf16.bf16.f32 " \
        "{%0,%1,%2,%3},{%4,%5,%6,%7},{%8,%9},{%0,%1,%2,%3};" \
        : "+f"((D)[0]), "+f"((D)[1]), "+f"((D)[2]), "+f"((D)[3]) \
        : "r"((A)[0]), "r"((A)[1]), "r"((A)[2]), "r"((A)[3]), \
          "r"((B)[0]), "r"((B)[1]))

__device__ __forceinline__ void cp16(uint32_t sp, const void* gp) {
    asm volatile("cp.async.cg.shared.global [%0], [%1], 16;"
                 :: "r"(sp), "l"(__cvta_generic_to_global(gp)));
}

// ---------------------------------------------------------------------------
// K0: fp32 -> split bf16 (hi + lo), padded rows [LDIM, LPAD) zeroed.
//     which==0 additionally zeroes the reduction scratch.
// ---------------------------------------------------------------------------
__global__ __launch_bounds__(256)
void convert_kernel(const float* __restrict__ src, int which) {
    int idx = blockIdx.x * blockDim.x + threadIdx.x;   // NB*LPAD*64 float4 groups
    if (which == 0) {
        if (idx < NLTOT) { g_rowsum[idx] = 0.f; g_rowbest[idx] = 0ull; }
        if (idx < NSTOT) { g_colsum[idx] = 0.f; g_colmaxU[idx] = 0u; }
    }
    int k4 = idx & 63;
    int r  = (idx >> 6) % LPAD;
    int b  = idx / (64 * LPAD);
    if (b >= NB) return;

    __nv_bfloat16* hi = which ? g_f1h : g_f0h;
    __nv_bfloat16* lo = which ? g_f1l : g_f0l;

    float4 v = make_float4(0.f, 0.f, 0.f, 0.f);
    if (r < LDIM)
        v = *reinterpret_cast<const float4*>(src + ((size_t)(b * LDIM + r)) * CDIM + k4 * 4);

    float x[4] = {v.x, v.y, v.z, v.w};
    __nv_bfloat16 h[4], l[4];
#pragma unroll
    for (int i = 0; i < 4; i++) {
        h[i] = __float2bfloat16(x[i]);
        l[i] = __float2bfloat16(x[i] - __bfloat162float(h[i]));
    }
    size_t o = ((size_t)(b * LPAD + r)) * CDIM + k4 * 4;
    reinterpret_cast<__nv_bfloat162*>(hi + o)[0] = __halves2bfloat162(h[0], h[1]);
    reinterpret_cast<__nv_bfloat162*>(hi + o)[1] = __halves2bfloat162(h[2], h[3]);
    reinterpret_cast<__nv_bfloat162*>(lo + o)[0] = __halves2bfloat162(l[0], l[1]);
    reinterpret_cast<__nv_bfloat162*>(lo + o)[1] = __halves2bfloat162(l[2], l[3]);
}

// ---------------------------------------------------------------------------
// K1: split-bf16 HMMA GEMM + fused exp + row/col exp-sum accumulation.
//     (R4/R6 mainloop -- measured best: BK=32, 2 stages, 80B smem stride)
// ---------------------------------------------------------------------------
#define SMS 80                       // smem row stride bytes (32 bf16 + pad)
#define MATB (128 * SMS)             // 10240 B per matrix tile
#define STAGEB (4 * MATB)            // 40960 B per stage
#define GEMM_SMEM (2 * STAGEB)       // 81920 B

__global__ __launch_bounds__(256, 2)
void gemm_kernel(float* __restrict__ sim)
{
    extern __shared__ __align__(16) char dsm[];
    const int tid = threadIdx.x;
    const int b  = blockIdx.z;
    const int m0 = blockIdx.y * 128;
    const int n0 = blockIdx.x * 128;
    const uint32_t sbase = smem_u32(dsm);

    const __nv_bfloat16* gAh = g_f0h + (size_t)(b * LPAD + m0) * CDIM;
    const __nv_bfloat16* gAl = g_f0l + (size_t)(b * LPAD + m0) * CDIM;
    const __nv_bfloat16* gBh = g_f1h + (size_t)(b * LPAD + n0) * CDIM;
    const __nv_bfloat16* gBl = g_f1l + (size_t)(b * LPAD + n0) * CDIM;

    int l_mat[8], l_r[8], l_c[8];
#pragma unroll
    for (int i = 0; i < 8; i++) {
        int id = tid + i * 256;
        l_mat[i] = id >> 9;
        l_r[i]   = (id >> 2) & 127;
        l_c[i]   = id & 3;
    }

#define LOAD_STAGE(KC, BUF) do {                                              \
        int koff = (KC) * 32;                                                 \
        _Pragma("unroll")                                                     \
        for (int i = 0; i < 8; i++) {                                         \
            const __nv_bfloat16* bp =                                         \
                (l_mat[i] == 0) ? gAh : (l_mat[i] == 1) ? gAl :               \
                (l_mat[i] == 2) ? gBh : gBl;                                  \
            const __nv_bfloat16* gp = bp + (size_t)l_r[i] * CDIM + koff + l_c[i] * 8; \
            uint32_t sp = sbase + (BUF) * STAGEB + l_mat[i] * MATB            \
                        + l_r[i] * SMS + l_c[i] * 16;                         \
            cp16(sp, gp);                                                     \
        }                                                                     \
        asm volatile("cp.async.commit_group;" ::: "memory");                  \
    } while (0)

    float acc[4][4][4];
#pragma unroll
    for (int mt = 0; mt < 4; mt++)
#pragma unroll
        for (int nt = 0; nt < 4; nt++)
#pragma unroll
            for (int q = 0; q < 4; q++) acc[mt][nt][q] = 0.f;

    LOAD_STAGE(0, 0);

    const int lane = tid & 31;
    const int wid  = tid >> 5;
    const int mwb  = (wid & 1) * 64;
    const int nwb  = (wid >> 1) * 32;
    const int a_row  = lane & 15;
    const int a_col8 = (lane & 16) >> 1;
    const int b_row  = (lane & 7) + ((lane & 16) >> 1);
    const int b_col8 = lane & 8;

    for (int kc = 0; kc < 8; kc++) {
        if (kc < 7) {
            LOAD_STAGE(kc + 1, (kc + 1) & 1);
            asm volatile("cp.async.wait_group 1;" ::: "memory");
        } else {
            asm volatile("cp.async.wait_group 0;" ::: "memory");
        }
        __syncthreads();

        const uint32_t st = sbase + (kc & 1) * STAGEB;
#pragma unroll
        for (int ks = 0; ks < 2; ks++) {
            const int kcol = ks * 16;
            uint32_t ah[4][4], bh[4][2];
#pragma unroll
            for (int mt = 0; mt < 4; mt++) {
                uint32_t ad = st + (mwb + mt * 16 + a_row) * SMS
                            + (kcol + a_col8) * 2;
                LDSM4(ah[mt], ad);
            }
#pragma unroll
            for (int bp = 0; bp < 2; bp++) {
                uint32_t bd = st + 2 * MATB + (nwb + bp * 16 + b_row) * SMS
                            + (kcol + b_col8) * 2;
                uint32_t r[4]; LDSM4(r, bd);
                bh[bp * 2][0] = r[0]; bh[bp * 2][1] = r[1];
                bh[bp * 2 + 1][0] = r[2]; bh[bp * 2 + 1][1] = r[3];
            }
#pragma unroll
            for (int mt = 0; mt < 4; mt++)
#pragma unroll
                for (int nt = 0; nt < 4; nt++)
                    MMA16816(acc[mt][nt], ah[mt], bh[nt]);
            {
                uint32_t bl[4][2];
#pragma unroll
                for (int bp = 0; bp < 2; bp++) {
                    uint32_t bd = st + 3 * MATB + (nwb + bp * 16 + b_row) * SMS
                                + (kcol + b_col8) * 2;
                    uint32_t r[4]; LDSM4(r, bd);
                    bl[bp * 2][0] = r[0]; bl[bp * 2][1] = r[1];
                    bl[bp * 2 + 1][0] = r[2]; bl[bp * 2 + 1][1] = r[3];
                }
#pragma unroll
                for (int mt = 0; mt < 4; mt++)
#pragma unroll
                    for (int nt = 0; nt < 4; nt++)
                        MMA16816(acc[mt][nt], ah[mt], bl[nt]);
            }
            {
                uint32_t al[4][4];
#pragma unroll
                for (int mt = 0; mt < 4; mt++) {
                    uint32_t ad = st + MATB + (mwb + mt * 16 + a_row) * SMS
                                + (kcol + a_col8) * 2;
                    LDSM4(al[mt], ad);
                }
#pragma unroll
                for (int mt = 0; mt < 4; mt++)
#pragma unroll
                    for (int nt = 0; nt < 4; nt++)
                        MMA16816(acc[mt][nt], al[mt], bh[nt]);
            }
        }
        __syncthreads();
    }

    // ---- fused epilogue: e = exp(sim*scale); store e; accumulate sums ----
    float* simb = sim + (size_t)b * LDIM * SDIM;
    float rsum[4][2];
    float csum[4][2];
#pragma unroll
    for (int i = 0; i < 4; i++) {
        rsum[i][0] = rsum[i][1] = 0.f;
        csum[i][0] = csum[i][1] = 0.f;
    }

#pragma unroll
    for (int mt = 0; mt < 4; mt++) {
        int rr = m0 + mwb + mt * 16 + (lane >> 2);
        bool vr0 = rr < LDIM;
        bool vr1 = (rr + 8) < LDIM;
#pragma unroll
        for (int nt = 0; nt < 4; nt++) {
            int cc = n0 + nwb + nt * 8 + (lane & 3) * 2;
            bool vc = (cc + 1) < SDIM;
            float e0 = __expf(acc[mt][nt][0] * SIM_SCALE);
            float e1 = __expf(acc[mt][nt][1] * SIM_SCALE);
            float e2 = __expf(acc[mt][nt][2] * SIM_SCALE);
            float e3 = __expf(acc[mt][nt][3] * SIM_SCALE);
            if (vc) {
                if (vr0)
                    *reinterpret_cast<float2*>(simb + (size_t)rr * SDIM + cc)
                        = make_float2(e0, e1);
                if (vr1)
                    *reinterpret_cast<float2*>(simb + (size_t)(rr + 8) * SDIM + cc)
                        = make_float2(e2, e3);
                rsum[mt][0] += e0 + e1;
                rsum[mt][1] += e2 + e3;
                csum[nt][0] += (vr0 ? e0 : 0.f) + (vr1 ? e2 : 0.f);
                csum[nt][1] += (vr0 ? e1 : 0.f) + (vr1 ? e3 : 0.f);
            }
        }
    }

#pragma unroll
    for (int mt = 0; mt < 4; mt++)
#pragma unroll
        for (int h = 0; h < 2; h++) {
            float v = rsum[mt][h];
            v += __shfl_xor_sync(0xffffffffu, v, 1);
            v += __shfl_xor_sync(0xffffffffu, v, 2);
            if ((lane & 3) == 0) {
                int rr = m0 + mwb + mt * 16 + (lane >> 2) + h * 8;
                if (rr < LDIM) atomicAdd(&g_rowsum[b * LDIM + rr], v);
            }
        }
#pragma unroll
    for (int nt = 0; nt < 4; nt++)
#pragma unroll
        for (int q1 = 0; q1 < 2; q1++) {
            float v = csum[nt][q1];
            v += __shfl_xor_sync(0xffffffffu, v, 4);
            v += __shfl_xor_sync(0xffffffffu, v, 8);
            v += __shfl_xor_sync(0xffffffffu, v, 16);
            if (lane < 4) {
                int cc = n0 + nwb + nt * 8 + lane * 2 + q1;
                if (cc < SDIM) atomicAdd(&g_colsum[b * SDIM + cc], v);
            }
        }
#undef LOAD_STAGE
}

// ---------------------------------------------------------------------------
// K2: conf pass.  invSc in shared memory; TWO rows interleaved per iteration
//     (8 outstanding float4 loads instead of 4 -> latency hiding).
//       u = (e*e) * invSr;  c = u * invSc;  write c in place
// ---------------------------------------------------------------------------
#define RPB 24           // rows per block (3600 = 150 * 24), processed 2 at a time
#define S4  (SDIM / 4)   // 900 float4 per row

__global__ __launch_bounds__(256)
void conf_kernel(float* __restrict__ sim) {
    __shared__ __align__(16) float sInv[SDIM];   // 14.4 KB

    const int tid = threadIdx.x;
    const int b   = blockIdx.y;
    const int r0  = blockIdx.x * RPB;

    for (int i = tid; i < S4; i += 256) {
        float4 cs = *reinterpret_cast<const float4*>(g_colsum + b * SDIM + 4 * i);
        float4 iv = make_float4(1.0f / cs.x, 1.0f / cs.y, 1.0f / cs.z, 1.0f / cs.w);
        *reinterpret_cast<float4*>(sInv + 4 * i) = iv;
    }
    __syncthreads();

    uint32_t cmU[4][4];
#pragma unroll
    for (int i = 0; i < 4; i++)
#pragma unroll
        for (int c = 0; c < 4; c++) cmU[i][c] = 0u;

    for (int r = 0; r < RPB; r += 2) {
        const int l = r0 + r;
        float* row0 = sim + ((size_t)(b * LDIM + l)) * SDIM;
        float* row1 = row0 + SDIM;
        const float invSr0 = 1.0f / g_rowsum[b * LDIM + l];
        const float invSr1 = 1.0f / g_rowsum[b * LDIM + l + 1];
        float best0 = -1.f, best1 = -1.f;
        int   bj0 = 0, bj1 = 0;
#pragma unroll
        for (int i = 0; i < 4; i++) {
            int s4 = tid + i * 256;
            if (s4 < S4) {
                float4 e0 = *reinterpret_cast<const float4*>(row0 + 4 * s4);
                float4 e1 = *reinterpret_cast<const float4*>(row1 + 4 * s4);
                float4 iv = *reinterpret_cast<const float4*>(sInv + 4 * s4);
                float ev0[4] = {e0.x, e0.y, e0.z, e0.w};
                float ev1[4] = {e1.x, e1.y, e1.z, e1.w};
                float ivv[4] = {iv.x, iv.y, iv.z, iv.w};
                float cv0[4], cv1[4];
#pragma unroll
                for (int c = 0; c < 4; c++) {
                    float u0 = (ev0[c] * ev0[c]) * invSr0;
                    float u1 = (ev1[c] * ev1[c]) * invSr1;
                    float c0 = u0 * ivv[c];
                    float c1 = u1 * ivv[c];
                    cv0[c] = c0; cv1[c] = c1;
                    uint32_t ub0 = __float_as_uint(u0);
                    uint32_t ub1 = __float_as_uint(u1);
                    uint32_t ub = ub0 > ub1 ? ub0 : ub1;
                    if (ub > cmU[i][c]) cmU[i][c] = ub;
                    if (c0 > best0) { best0 = c0; bj0 = 4 * s4 + c; }
                    if (c1 > best1) { best1 = c1; bj1 = 4 * s4 + c; }
                }
                *reinterpret_cast<float4*>(row0 + 4 * s4) =
                    make_float4(cv0[0], cv0[1], cv0[2], cv0[3]);
                *reinterpret_cast<float4*>(row1 + 4 * s4) =
                    make_float4(cv1[0], cv1[1], cv1[2], cv1[3]);
            }
        }
#pragma unroll
        for (int o = 16; o > 0; o >>= 1) {
            float v2 = __shfl_xor_sync(0xffffffffu, best0, o);
            int   j2 = __shfl_xor_sync(0xffffffffu, bj0, o);
            if (v2 > best0 || (v2 == best0 && j2 < bj0)) { best0 = v2; bj0 = j2; }
            float v3 = __shfl_xor_sync(0xffffffffu, best1, o);
            int   j3 = __shfl_xor_sync(0xffffffffu, bj1, o);
            if (v3 > best1 || (v3 == best1 && j3 < bj1)) { best1 = v3; bj1 = j3; }
        }
        if ((tid & 31) == 0) {
            unsigned long long pk0 =
                ((unsigned long long)__float_as_uint(best0) << 32) |
                (unsigned int)(SDIM - 1 - bj0);
            atomicMax(&g_rowbest[b * LDIM + l], pk0);
            unsigned long long pk1 =
                ((unsigned long long)__float_as_uint(best1) << 32) |
                (unsigned int)(SDIM - 1 - bj1);
            atomicMax(&g_rowbest[b * LDIM + l + 1], pk1);
        }
    }
#pragma unroll
    for (int i = 0; i < 4; i++) {
        int s4 = tid + i * 256;
        if (s4 < S4) {
#pragma unroll
            for (int c = 0; c < 4; c++)
                atomicMax(&g_colmaxU[b * SDIM + 4 * s4 + c], cmU[i][c]);
        }
    }
}

// ---------------------------------------------------------------------------
// K3: finalize matches
// ---------------------------------------------------------------------------
__device__ __forceinline__ bool border_ok(int idx) {
    int r = idx / W0, c = idx % W0;
    return (r >= BORDER) && (r < H0 - BORDER) && (c >= BORDER) && (c < W0 - BORDER);
}

__global__ void finalize_kernel(float* __restrict__ out_maskv,
                                float* __restrict__ out_ids,
                                float* __restrict__ out_mconf) {
    int idx = blockIdx.x * blockDim.x + threadIdx.x;
    if (idx >= NLTOT) return;
    int b = idx / LDIM;
    int l = idx - b * LDIM;

    unsigned long long pk = g_rowbest[idx];
    float c = __uint_as_float((unsigned int)(pk >> 32));
    int   j = SDIM - 1 - (int)(pk & 0xffffffffu);

    float umax  = __uint_as_float(g_colmaxU[b * SDIM + j]);
    float invSc = 1.0f / g_colsum[b * SDIM + j];
    float cmax  = umax * invSc;   // identical multiply order as conf_kernel

    bool ok = (c > THR) && border_ok(l) && border_ok(j) && (c == cmax);

    out_maskv[idx] = ok ? 1.f : 0.f;
    out_ids[idx]   = ok ? (float)j : 0.f;
    out_mconf[idx] = ok ? c : 0.f;
}

// ---------------------------------------------------------------------------
extern "C" void kernel_launch(void* const* d_in, const int* in_sizes, int n_in,
                              void* d_out, int out_size) {
    const float* f0 = (const float*)d_in[0];
    const float* f1 = (const float*)d_in[1];
    (void)in_sizes; (void)n_in; (void)out_size;

    float* conf  = (float*)d_out;                      // [NB, L, S]
    float* maskv = conf  + (size_t)NB * LDIM * SDIM;   // [NB, L]
    float* ids   = maskv + NB * LDIM;
    float* mconf = ids   + NB * LDIM;

    const int cvt_blocks = (NB * LPAD * 64 + 255) / 256;
    convert_kernel<<<cvt_blocks, 256>>>(f0, 0);   // also zeroes reductions
    convert_kernel<<<cvt_blocks, 256>>>(f1, 1);

    static bool attr_set = false;
    if (!attr_set) {
        cudaFuncSetAttribute(gemm_kernel,
                             cudaFuncAttributeMaxDynamicSharedMemorySize, GEMM_SMEM);
        attr_set = true;
    }
    dim3 gGemm(LPAD / 128, LPAD / 128, NB);            // 29 x 29 x 4
    gemm_kernel<<<gGemm, 256, GEMM_SMEM>>>(conf);

    conf_kernel<<<dim3(LDIM / RPB, NB), 256>>>(conf);
    finalize_kernel<<<(NLTOT + 255) / 256, 256>>>(maskv, ids, mconf);
}